// round 13
// baseline (speedup 1.0000x reference)
#include <cuda_runtime.h>
#include <cuda_bf16.h>

#define N_NODES    100000
#define N_EDGES    1600000
#define F_IN       100
#define HEADS      3
#define HEAD_DIM   64
#define HIDDEN     192
#define NUM_GRAPHS 128
#define NUM_CLASSES 2
#define SLOPE_ATT  0.2f
#define SLOPE_ACT  0.01f

#define SCAN_NB    ((N_NODES + 1023) / 1024)   // 98
#define HWORDS     96                          // bf16x2 words per node row

// ---------------- scratch (static __device__: allocation-free) ----------------
__device__ unsigned     g_hb[N_NODES * HWORDS];       // h in bf16x2, 38.4 MB
__device__ float        g_asrc[N_NODES * HEADS];
__device__ float        g_adst[N_NODES * HEADS];
__device__ int          g_deg[N_NODES];
__device__ int          g_row[N_NODES];               // per-block exclusive scan
__device__ int          g_cur[N_NODES];
__device__ int4         g_epack[N_EDGES];             // CSR: {src, w0,w1,w2 bits}
__device__ unsigned     g_pool[NUM_GRAPHS * HIDDEN];  // encoded-float max
__device__ int          g_part[128];                  // scan block offsets

// ---------------- helpers ----------------
__device__ __forceinline__ float lrelu(float x, float s) { return x > 0.f ? x : s * x; }

__device__ __forceinline__ unsigned enc_f(float f) {
    unsigned b = __float_as_uint(f);
    return (b & 0x80000000u) ? ~b : (b | 0x80000000u);
}
__device__ __forceinline__ float dec_f(unsigned k) {
    unsigned b = (k & 0x80000000u) ? (k & 0x7FFFFFFFu) : ~k;
    return __uint_as_float(b);
}

// bf16x2 word -> two exact fp32 (bf16 is truncated fp32: just shift)
__device__ __forceinline__ float blo(unsigned q) { return __uint_as_float(q << 16); }
__device__ __forceinline__ float bhi(unsigned q) { return __uint_as_float(q & 0xFFFF0000u); }

// pack two fp32 -> bf16x2 word (lo = x, hi = y), round-to-nearest
__device__ __forceinline__ unsigned pack_bf(float x, float y) {
    unsigned w;
    asm("cvt.rn.bf16x2.f32 %0, %1, %2;" : "=r"(w) : "f"(y), "f"(x));
    return w;
}

// packed f32x2 FMA (Blackwell PTX-only; 2x fp32 throughput)
__device__ __forceinline__ unsigned long long ffma2(unsigned long long a,
                                                    unsigned long long b,
                                                    unsigned long long c) {
    unsigned long long d;
    asm("fma.rn.f32x2 %0, %1, %2, %3;" : "=l"(d) : "l"(a), "l"(b), "l"(c));
    return d;
}
__device__ __forceinline__ unsigned long long packdup(float x) {
    unsigned long long r;
    asm("mov.b64 %0, {%1, %1};" : "=l"(r) : "f"(x));
    return r;
}
__device__ __forceinline__ float2 unpack2(unsigned long long v) {
    float2 r;
    asm("mov.b64 {%0, %1}, %2;" : "=f"(r.x), "=f"(r.y) : "l"(v));
    return r;
}

__device__ __forceinline__ int warp_iscan(int v, int lane) {
    #pragma unroll
    for (int d = 1; d < 32; d <<= 1) {
        int t = __shfl_up_sync(0xFFFFFFFFu, v, d);
        if (lane >= d) v += t;
    }
    return v;
}

// ---------------- 0: init scratch ----------------
__global__ void init_kernel() {
    int stride = gridDim.x * blockDim.x;
    for (int i = blockIdx.x * blockDim.x + threadIdx.x; i < N_NODES; i += stride) {
        g_deg[i] = 0;
        g_cur[i] = 0;
    }
    for (int i = blockIdx.x * blockDim.x + threadIdx.x; i < NUM_GRAPHS * HIDDEN; i += stride)
        g_pool[i] = 0u;   // encodes "most negative"
}

// ---------------- 1: h = x @ W  (fp32 math, bf16x2 store) ----------------
#define GEMM_T 192
#define GEMM_R 32
#define KHALF  50
__global__ __launch_bounds__(GEMM_T)
void gemm_kernel(const float* __restrict__ x, const float* __restrict__ W) {
    __shared__ unsigned long long sW[KHALF * 96];   // 38400 B
    __shared__ float sX[GEMM_R * KHALF];            //  6400 B

    int tid = threadIdx.x;
    int rowbase = blockIdx.x * GEMM_R;
    int rs = tid & 3;           // row slot 0..3 -> rows rs + 4i
    int pc = tid >> 2;          // pair-group 0..47 -> pairs pc*2, pc*2+1

    unsigned long long acc[8][2];
    #pragma unroll
    for (int i = 0; i < 8; i++) { acc[i][0] = 0ull; acc[i][1] = 0ull; }

    const float2* W2 = (const float2*)W;   // [100][96] pairs
    const float2* x2 = (const float2*)x;

    #pragma unroll 1
    for (int ph = 0; ph < 2; ph++) {
        int k0 = ph * KHALF;
        __syncthreads();
        for (int i = tid; i < KHALF * 96; i += GEMM_T) {
            int k = i / 96, p = i % 96;
            float2 v = W2[(k0 + k) * 96 + p];
            unsigned long long q;
            asm("mov.b64 %0, {%1, %2};" : "=l"(q) : "f"(v.x), "f"(v.y));
            sW[i] = q;
        }
        float2* sX2 = (float2*)sX;
        for (int i = tid; i < GEMM_R * (KHALF / 2); i += GEMM_T) {
            int r = i / 25, j = i % 25;
            sX2[r * 25 + j] = x2[(long long)(rowbase + r) * 50 + ph * 25 + j];
        }
        __syncthreads();

        #pragma unroll 2
        for (int k = 0; k < KHALF; k++) {
            unsigned long long w0 = sW[k * 96 + pc * 2];
            unsigned long long w1 = sW[k * 96 + pc * 2 + 1];
            #pragma unroll
            for (int i = 0; i < 8; i++) {
                unsigned long long xx = packdup(sX[(rs + 4 * i) * KHALF + k]);
                acc[i][0] = ffma2(xx, w0, acc[i][0]);
                acc[i][1] = ffma2(xx, w1, acc[i][1]);
            }
        }
    }

    #pragma unroll
    for (int i = 0; i < 8; i++) {
        int r = rowbase + rs + 4 * i;
        float2 a = unpack2(acc[i][0]);
        float2 b = unpack2(acc[i][1]);
        uint2* o = (uint2*)(g_hb + (long long)r * HWORDS) + pc;
        uint2 w;
        w.x = pack_bf(a.x, a.y);
        w.y = pack_bf(b.x, b.y);
        *o = w;
    }
}

// ---------------- 2: attention logits a_src/a_dst (warp per node) ----------------
__global__ void adot_kernel(const float* __restrict__ att_src,
                            const float* __restrict__ att_dst) {
    int lane = threadIdx.x & 31;
    int n = blockIdx.x * (blockDim.x >> 5) + (threadIdx.x >> 5);
    if (n >= N_NODES) return;

    const unsigned* hp = g_hb + (long long)n * HWORDS;
    const float2* as2 = (const float2*)att_src;
    const float2* ad2 = (const float2*)att_dst;

    float ps[HEADS], pd[HEADS];
    #pragma unroll
    for (int h = 0; h < HEADS; h++) {
        unsigned q = hp[h * 32 + lane];
        float vx = blo(q), vy = bhi(q);
        float2 a = as2[h * 32 + lane];
        float2 b = ad2[h * 32 + lane];
        ps[h] = vx * a.x + vy * a.y;
        pd[h] = vx * b.x + vy * b.y;
    }
    #pragma unroll
    for (int d = 16; d > 0; d >>= 1) {
        #pragma unroll
        for (int h = 0; h < HEADS; h++) {
            ps[h] += __shfl_xor_sync(0xFFFFFFFFu, ps[h], d);
            pd[h] += __shfl_xor_sync(0xFFFFFFFFu, pd[h], d);
        }
    }
    if (lane == 0) {
        #pragma unroll
        for (int h = 0; h < HEADS; h++) {
            g_asrc[n * HEADS + h] = ps[h];
            g_adst[n * HEADS + h] = pd[h];
        }
    }
}

// ---------------- 3: degree histogram ----------------
__global__ void hist_kernel(const int* __restrict__ ei) {
    int i = blockIdx.x * blockDim.x + threadIdx.x;
    if (i >= N_EDGES) return;
    atomicAdd(&g_deg[ei[N_EDGES + i]], 1);
}

// ---------------- 4: two-level exclusive scan (scan_add folded into consumers) --
__global__ void scan_blocks() {
    __shared__ int ws[32];
    int tid = threadIdx.x, lane = tid & 31, w = tid >> 5;
    int i = blockIdx.x * 1024 + tid;
    int v = (i < N_NODES) ? g_deg[i] : 0;
    int inc = warp_iscan(v, lane);
    if (lane == 31) ws[w] = inc;
    __syncthreads();
    if (w == 0) ws[lane] = warp_iscan(ws[lane], lane);
    __syncthreads();
    int base = (w > 0) ? ws[w - 1] : 0;
    if (i < N_NODES) g_row[i] = base + inc - v;
    if (tid == 0) g_part[blockIdx.x] = ws[31];
}
__global__ void scan_part() {
    __shared__ int ws[4];
    int t = threadIdx.x, lane = t & 31, w = t >> 5;
    int v = (t < SCAN_NB) ? g_part[t] : 0;
    int inc = warp_iscan(v, lane);
    if (lane == 31) ws[w] = inc;
    __syncthreads();
    if (w == 0 && lane < 4) {
        int s = ws[lane];
        #pragma unroll
        for (int d = 1; d < 4; d <<= 1) {
            int tt = __shfl_up_sync(0x0000000Fu, s, d);
            if (lane >= d) s += tt;
        }
        ws[lane] = s;
    }
    __syncthreads();
    int base = (w > 0) ? ws[w - 1] : 0;
    if (t < SCAN_NB) g_part[t] = base + inc - v;
}

// ---- 5: scatter edges into CSR by dst, fused with edge-weight computation ----
__global__ void scatterw_kernel(const int* __restrict__ ei) {
    int i = blockIdx.x * blockDim.x + threadIdx.x;
    if (i >= N_EDGES) return;
    int s = ei[i];
    int d = ei[N_EDGES + i];
    int pos = g_row[d] + g_part[d >> 10] + atomicAdd(&g_cur[d], 1);
    float w0 = __expf(lrelu(g_asrc[s * 3 + 0] + g_adst[d * 3 + 0], SLOPE_ATT));
    float w1 = __expf(lrelu(g_asrc[s * 3 + 1] + g_adst[d * 3 + 1], SLOPE_ATT));
    float w2 = __expf(lrelu(g_asrc[s * 3 + 2] + g_adst[d * 3 + 2], SLOPE_ATT));
    g_epack[pos] = make_int4(s, __float_as_int(w0), __float_as_int(w1), __float_as_int(w2));
}

// ------- 6: aggregation, 2 warps per node (halved latency chain) + pooling -------
// Block = 256 threads = 8 warps = 4 nodes x 2 warps. Warp pair splits the edge
// list; partials (3x float2 + 3 den = 9 floats/lane) combine via smem
// (stride 9 coprime with 32 banks -> conflict-free).
__global__ __launch_bounds__(256)
void aggregate_kernel(const int* __restrict__ batch,
                      const float* __restrict__ bias) {
    __shared__ unsigned spool[HIDDEN];
    __shared__ float spart[4][32][9];
    __shared__ int sg0;

    int tid  = threadIdx.x;
    int lane = tid & 31;
    int wid  = tid >> 5;
    int slot = wid >> 1;          // node slot 0..3
    int half = wid & 1;
    int n = blockIdx.x * 4 + slot;   // grid covers exactly N_NODES (25000*4)

    if (tid == 0) sg0 = batch[blockIdx.x * 4];
    if (tid < HIDDEN) spool[tid] = 0u;       // encoded -inf
    __syncthreads();

    int start = g_row[n] + g_part[n >> 10];
    int deg   = g_deg[n];
    int mid   = deg >> 1;
    int jb = half ? mid : 0;
    int je = half ? deg : mid;

    float den0, den1, den2;
    float2 a0, a1, a2;
    if (half == 0) {
        // self-loop contribution
        float ws0 = __expf(lrelu(g_asrc[n * 3 + 0] + g_adst[n * 3 + 0], SLOPE_ATT));
        float ws1 = __expf(lrelu(g_asrc[n * 3 + 1] + g_adst[n * 3 + 1], SLOPE_ATT));
        float ws2 = __expf(lrelu(g_asrc[n * 3 + 2] + g_adst[n * 3 + 2], SLOPE_ATT));
        den0 = ws0; den1 = ws1; den2 = ws2;
        const unsigned* hp = g_hb + (long long)n * HWORDS;
        unsigned qs0 = hp[lane], qs1 = hp[32 + lane], qs2 = hp[64 + lane];
        a0 = make_float2(ws0 * blo(qs0), ws0 * bhi(qs0));
        a1 = make_float2(ws1 * blo(qs1), ws1 * bhi(qs1));
        a2 = make_float2(ws2 * blo(qs2), ws2 * bhi(qs2));
    } else {
        den0 = den1 = den2 = 0.f;
        a0 = make_float2(0.f, 0.f);
        a1 = make_float2(0.f, 0.f);
        a2 = make_float2(0.f, 0.f);
    }

    const int4* ep = g_epack;
    int j = jb;
    for (; j + 2 <= je; j += 2) {
        int4 e0 = ep[start + j];
        int4 e1 = ep[start + j + 1];
        const unsigned* p0 = g_hb + (long long)e0.x * HWORDS;
        const unsigned* p1 = g_hb + (long long)e1.x * HWORDS;
        unsigned q00 = p0[lane], q01 = p0[32 + lane], q02 = p0[64 + lane];
        unsigned q10 = p1[lane], q11 = p1[32 + lane], q12 = p1[64 + lane];
        float x00 = __int_as_float(e0.y), x01 = __int_as_float(e0.z), x02 = __int_as_float(e0.w);
        float x10 = __int_as_float(e1.y), x11 = __int_as_float(e1.z), x12 = __int_as_float(e1.w);
        den0 += x00 + x10; den1 += x01 + x11; den2 += x02 + x12;
        a0.x += x00 * blo(q00); a0.y += x00 * bhi(q00);
        a1.x += x01 * blo(q01); a1.y += x01 * bhi(q01);
        a2.x += x02 * blo(q02); a2.y += x02 * bhi(q02);
        a0.x += x10 * blo(q10); a0.y += x10 * bhi(q10);
        a1.x += x11 * blo(q11); a1.y += x11 * bhi(q11);
        a2.x += x12 * blo(q12); a2.y += x12 * bhi(q12);
    }
    if (j < je) {
        int4 e0 = ep[start + j];
        const unsigned* p0 = g_hb + (long long)e0.x * HWORDS;
        unsigned q00 = p0[lane], q01 = p0[32 + lane], q02 = p0[64 + lane];
        float x00 = __int_as_float(e0.y), x01 = __int_as_float(e0.z), x02 = __int_as_float(e0.w);
        den0 += x00; den1 += x01; den2 += x02;
        a0.x += x00 * blo(q00); a0.y += x00 * bhi(q00);
        a1.x += x01 * blo(q01); a1.y += x01 * bhi(q01);
        a2.x += x02 * blo(q02); a2.y += x02 * bhi(q02);
    }

    if (half == 1) {
        float* sp = spart[slot][lane];
        sp[0] = a0.x; sp[1] = a0.y; sp[2] = a1.x; sp[3] = a1.y;
        sp[4] = a2.x; sp[5] = a2.y; sp[6] = den0; sp[7] = den1; sp[8] = den2;
    }
    __syncthreads();

    if (half == 0) {
        const float* sp = spart[slot][lane];
        a0.x += sp[0]; a0.y += sp[1]; a1.x += sp[2]; a1.y += sp[3];
        a2.x += sp[4]; a2.y += sp[5]; den0 += sp[6]; den1 += sp[7]; den2 += sp[8];

        int g = batch[n];
        const float2* b2 = (const float2*)bias;
        float2 bb0 = b2[lane], bb1 = b2[32 + lane], bb2 = b2[64 + lane];

        float r0 = 1.f / den0, r1 = 1.f / den1, r2 = 1.f / den2;
        unsigned e[6];
        e[0] = enc_f(lrelu(a0.x * r0 + bb0.x, SLOPE_ACT));
        e[1] = enc_f(lrelu(a0.y * r0 + bb0.y, SLOPE_ACT));
        e[2] = enc_f(lrelu(a1.x * r1 + bb1.x, SLOPE_ACT));
        e[3] = enc_f(lrelu(a1.y * r1 + bb1.y, SLOPE_ACT));
        e[4] = enc_f(lrelu(a2.x * r2 + bb2.x, SLOPE_ACT));
        e[5] = enc_f(lrelu(a2.y * r2 + bb2.y, SLOPE_ACT));

        int f0 = lane * 2, f1 = 64 + lane * 2, f2 = 128 + lane * 2;
        if (g == sg0) {
            atomicMax(&spool[f0    ], e[0]); atomicMax(&spool[f0 + 1], e[1]);
            atomicMax(&spool[f1    ], e[2]); atomicMax(&spool[f1 + 1], e[3]);
            atomicMax(&spool[f2    ], e[4]); atomicMax(&spool[f2 + 1], e[5]);
        } else {
            unsigned* pool = g_pool + g * HIDDEN;
            atomicMax(&pool[f0    ], e[0]); atomicMax(&pool[f0 + 1], e[1]);
            atomicMax(&pool[f1    ], e[2]); atomicMax(&pool[f1 + 1], e[3]);
            atomicMax(&pool[f2    ], e[4]); atomicMax(&pool[f2 + 1], e[5]);
        }
    }
    __syncthreads();
    if (tid < HIDDEN) atomicMax(&g_pool[sg0 * HIDDEN + tid], spool[tid]);
}

// ---------------- 7: classifier ----------------
__global__ void classify_kernel(const float* __restrict__ clsW,
                                const float* __restrict__ clsb,
                                float* __restrict__ out) {
    int t = threadIdx.x;
    if (t >= NUM_GRAPHS * NUM_CLASSES) return;
    int g = t >> 1, c = t & 1;
    float s = clsb[c];
    #pragma unroll 4
    for (int k = 0; k < HIDDEN; k++)
        s += dec_f(g_pool[g * HIDDEN + k]) * clsW[k * NUM_CLASSES + c];
    out[g * NUM_CLASSES + c] = s;
}

// ---------------- launch ----------------
extern "C" void kernel_launch(void* const* d_in, const int* in_sizes, int n_in,
                              void* d_out, int out_size) {
    const float* x       = (const float*)d_in[0];
    const int*   ei      = (const int*)d_in[1];     // int32 (JAX x64 disabled)
    const int*   batch   = (const int*)d_in[2];     // int32
    const float* W       = (const float*)d_in[3];
    const float* att_src = (const float*)d_in[4];
    const float* att_dst = (const float*)d_in[5];
    const float* bias    = (const float*)d_in[6];
    const float* clsW    = (const float*)d_in[7];
    const float* clsb    = (const float*)d_in[8];
    float* out = (float*)d_out;

    init_kernel<<<256, 256>>>();
    hist_kernel<<<(N_EDGES + 255) / 256, 256>>>(ei);
    scan_blocks<<<SCAN_NB, 1024>>>();
    scan_part<<<1, 128>>>();
    gemm_kernel<<<N_NODES / GEMM_R, GEMM_T>>>(x, W);
    adot_kernel<<<(N_NODES + 7) / 8, 256>>>(att_src, att_dst);
    scatterw_kernel<<<(N_EDGES + 255) / 256, 256>>>(ei);
    aggregate_kernel<<<N_NODES / 4, 256>>>(batch, bias);
    classify_kernel<<<1, 256>>>(clsW, clsb, out);
}